// round 14
// baseline (speedup 1.0000x reference)
#include <cuda_runtime.h>

#define TT 512
#define BB 64
#define II 512
#define HH 512

// ---- xproj_mma smem layout (float2 units) ----
// element (k8, r, j): idx = k8*600 + 9*r + 4*j   (r<64, j<8; unique & bank-tuned)
#define XIDX(k8, r, j) ((k8) * 600 + 9 * (r) + 4 * (j))
#define XTENS 4800                       // f2 per tensor plane set (8*600)
#define XSMEM (2 * XTENS * 8)            // 76800 B

// ---- rnn_persist smem layout ----
#define HS2 258     // float2 stride per batch row of h
#define RP  520     // ull stride per ks plane in reduction (512 used)
#define RED_OFF (8 * HS2 * 8)                  // 16512
#define SMEM_TOTAL (RED_OFF + 16 * RP * 8)     // 83072

// Static device scratch (no allocations allowed)
__device__ float g_xp[2][TT][BB][HH];      // input projections per direction
__device__ float g_h[2][2][BB][HH];        // [dir][buf][b][h] double-buffered state
__device__ unsigned g_flag[2][8][8][32];   // [dir][bgroup][nslice] flags, 128B padded
__device__ float2 g_xs[BB][TT][II];        // x split into {tf32 hi, tf32 lo} pairs
__device__ float2 g_ws[2][HH][II];         // W split likewise, per direction

typedef unsigned long long ull;

__device__ __forceinline__ void fma2(ull& acc, ull a, ull b) {
    asm("fma.rn.f32x2 %0, %1, %2, %0;" : "+l"(acc) : "l"(a), "l"(b));
}
__device__ __forceinline__ ull add2(ull a, ull b) {
    ull r; asm("add.rn.f32x2 %0, %1, %2;" : "=l"(r) : "l"(a), "l"(b)); return r;
}
__device__ __forceinline__ float2 unpack2(ull v) {
    float2 r; asm("mov.b64 {%0, %1}, %2;" : "=f"(r.x), "=f"(r.y) : "l"(v)); return r;
}
__device__ __forceinline__ unsigned ld_acq(const unsigned* p) {
    unsigned v; asm volatile("ld.acquire.gpu.u32 %0, [%1];" : "=r"(v) : "l"(p) : "memory");
    return v;
}
__device__ __forceinline__ void st_rel(unsigned* p, unsigned v) {
    asm volatile("st.release.gpu.u32 [%0], %1;" :: "l"(p), "r"(v) : "memory");
}
__device__ __forceinline__ float2 tf32_split(float v) {
    unsigned h, l;
    asm("cvt.rna.tf32.f32 %0, %1;" : "=r"(h) : "f"(v));
    float lo = v - __uint_as_float(h);
    asm("cvt.rna.tf32.f32 %0, %1;" : "=r"(l) : "f"(lo));
    return make_float2(__uint_as_float(h), __uint_as_float(l));
}
__device__ __forceinline__ void mma_tf32(float* c,
                                         unsigned a0, unsigned a1,
                                         unsigned a2, unsigned a3,
                                         unsigned b0, unsigned b1) {
    asm("mma.sync.aligned.m16n8k8.row.col.f32.tf32.tf32.f32 "
        "{%0,%1,%2,%3}, {%4,%5,%6,%7}, {%8,%9}, {%0,%1,%2,%3};"
        : "+f"(c[0]), "+f"(c[1]), "+f"(c[2]), "+f"(c[3])
        : "r"(a0), "r"(a1), "r"(a2), "r"(a3), "r"(b0), "r"(b1));
}

// ---------------------------------------------------------------------------
// Phase 0: split x / W into tf32 {hi, lo} pairs (run once per launch).
// ---------------------------------------------------------------------------
#define NX4 (BB * TT * II / 4)           // 4,194,304 float4 groups for x
#define NW4 (2 * HH * II / 4)            // 131,072 for both W
__global__ __launch_bounds__(256) void split_kernel(
    const float* __restrict__ x,
    const float* __restrict__ Wf, const float* __restrict__ Wb) {
    long long gi = (long long)blockIdx.x * 256 + threadIdx.x;
    if (gi < NX4) {
        float4 v = *((const float4*)x + gi);
        float2* o = &g_xs[0][0][0] + gi * 4;
        o[0] = tf32_split(v.x); o[1] = tf32_split(v.y);
        o[2] = tf32_split(v.z); o[3] = tf32_split(v.w);
    } else if (gi < NX4 + NW4) {
        long long wi = gi - NX4;                 // 0 .. NW4-1
        long long half = NW4 / 2;
        const float* W = (wi < half) ? Wf : Wb;
        long long li = (wi < half) ? wi : wi - half;
        float4 v = *((const float4*)W + li);
        float2* o = &g_ws[0][0][0] + wi * 4;
        o[0] = tf32_split(v.x); o[1] = tf32_split(v.y);
        o[2] = tf32_split(v.z); o[3] = tf32_split(v.w);
    }
}

// ---------------------------------------------------------------------------
// Phase 1: xp[dir][t][b][n] = sum_i x[b][t][i]*W[n][i] + bias[n], 3xTF32 mma.
// Grid (8, 512, 2); 256 threads; CTA = 64b x 64n at one t; K chunks of 64.
// Warp w: m-tile = 16*(w&3) rows of b, n-half = 32*(w>>2); 4 n8-tiles.
// ---------------------------------------------------------------------------
__global__ __launch_bounds__(256, 2) void xproj_mma(
    const float* __restrict__ bf, const float* __restrict__ bb) {
    extern __shared__ float2 smx[];
    float2* xs = smx;              // [8 planes][600]
    float2* wsm = smx + XTENS;
    const uint2* xsu = (const uint2*)xs;
    const uint2* wsu = (const uint2*)wsm;

    const int dir = blockIdx.z;
    const int t = blockIdx.y;
    const int n_base = blockIdx.x * 64;
    const float* __restrict__ bias = dir ? bb : bf;

    const int tid = threadIdx.x;
    const int warp = tid >> 5, lane = tid & 31;
    const int g = lane >> 2, tig = lane & 3;
    const int b0w = 16 * (warp & 3);
    const int n0w = 32 * (warp >> 2);

    // accumulators initialized with bias
    float c[4][4];
#pragma unroll
    for (int nt = 0; nt < 4; nt++) {
        float2 bv = *(const float2*)(bias + n_base + n0w + 8 * nt + 2 * tig);
        c[nt][0] = bv.x; c[nt][1] = bv.y;
        c[nt][2] = bv.x; c[nt][3] = bv.y;
    }

    // staging mapping: row sr = lane + 32*(warp&1), k-quarter sq = warp>>2... 
    // (use tid>>6 so each thread covers 1 row x 16 k)
    const int sr = (tid & 31) + 32 * ((tid >> 5) & 1);   // 0..63
    const int sq = tid >> 6;                             // 0..3
    const float2* xrow = &g_xs[sr][t][0];
    const float2* wrow = &g_ws[dir][n_base + sr][0];

    for (int kc = 0; kc < 8; kc++) {
        __syncthreads();
        // ---- stage: 16 elements per thread per tensor ----
#pragma unroll
        for (int e = 0; e < 4; e++) {
            int kl = sq * 16 + 4 * e;      // 0..63 (mult of 4)
            int kg = kc * 64 + kl;
            float4 p0 = *(const float4*)(xrow + kg);
            float4 p1 = *(const float4*)(xrow + kg + 2);
            float4 q0 = *(const float4*)(wrow + kg);
            float4 q1 = *(const float4*)(wrow + kg + 2);
            int k8 = kl >> 3, j0 = kl & 7;   // j0 in {0,4}
            xs[XIDX(k8, sr, j0 + 0)] = make_float2(p0.x, p0.y);
            xs[XIDX(k8, sr, j0 + 1)] = make_float2(p0.z, p0.w);
            xs[XIDX(k8, sr, j0 + 2)] = make_float2(p1.x, p1.y);
            xs[XIDX(k8, sr, j0 + 3)] = make_float2(p1.z, p1.w);
            wsm[XIDX(k8, sr, j0 + 0)] = make_float2(q0.x, q0.y);
            wsm[XIDX(k8, sr, j0 + 1)] = make_float2(q0.z, q0.w);
            wsm[XIDX(k8, sr, j0 + 2)] = make_float2(q1.x, q1.y);
            wsm[XIDX(k8, sr, j0 + 3)] = make_float2(q1.z, q1.w);
        }
        __syncthreads();
        // ---- mma over 8 k8-steps ----
#pragma unroll
        for (int k8 = 0; k8 < 8; k8++) {
            uint2 A0 = xsu[XIDX(k8, b0w + g, tig)];        // a0 {hi,lo}
            uint2 A1 = xsu[XIDX(k8, b0w + g + 8, tig)];    // a1
            uint2 A2 = xsu[XIDX(k8, b0w + g, tig + 4)];    // a2
            uint2 A3 = xsu[XIDX(k8, b0w + g + 8, tig + 4)];// a3
#pragma unroll
            for (int nt = 0; nt < 4; nt++) {
                uint2 B0 = wsu[XIDX(k8, n0w + 8 * nt + g, tig)];
                uint2 B1 = wsu[XIDX(k8, n0w + 8 * nt + g, tig + 4)];
                mma_tf32(c[nt], A0.x, A1.x, A2.x, A3.x, B0.x, B1.x);
                mma_tf32(c[nt], A0.x, A1.x, A2.x, A3.x, B0.y, B1.y);
                mma_tf32(c[nt], A0.y, A1.y, A2.y, A3.y, B0.x, B1.x);
            }
        }
    }

    // ---- epilogue: D rows = b, cols = n ----
    const int b1 = b0w + g, b2 = b1 + 8;
#pragma unroll
    for (int nt = 0; nt < 4; nt++) {
        int nc = n_base + n0w + 8 * nt + 2 * tig;
        *(float2*)&g_xp[dir][t][b1][nc] = make_float2(c[nt][0], c[nt][1]);
        *(float2*)&g_xp[dir][t][b2][nc] = make_float2(c[nt][2], c[nt][3]);
    }
}

// ---------------------------------------------------------------------------
// Phase 2: persistent recurrence (unchanged from best round).
// 128 CTAs (64/dir), 512 threads, 1 CTA/SM. 8 bg x 8 ns per dir; 8b x 64n.
// Weights in registers; h broadcast LDS; 16-plane reduce; 8-CTA flag barrier.
// ---------------------------------------------------------------------------
__global__ __launch_bounds__(512, 1) void rnn_persist(
    const float* __restrict__ Whf, const float* __restrict__ Whb,
    const float* __restrict__ h0f, const float* __restrict__ h0b,
    float* __restrict__ out) {
    extern __shared__ char smem[];
    float2* hs = (float2*)smem;                 // [8][HS2]
    ull* red   = (ull*)(smem + RED_OFF);        // [16][RP]

    const int cta = blockIdx.x;
    const int dir = cta & 1;
    const int rest = cta >> 1;
    const int bg = rest >> 3;
    const int ns = rest & 7;
    const int b_base = 8 * bg;
    const int n_base = 64 * ns;
    const float* __restrict__ Wh = dir ? Whb : Whf;
    const float* __restrict__ h0 = dir ? h0b : h0f;
    const int tid = threadIdx.x;
    const int wid = tid >> 5;
    const int lane = tid & 31;
    const int n0 = n_base + 2 * lane;

    ull w0[16], w1[16];
#pragma unroll
    for (int kkk = 0; kkk < 16; kkk++) {
        int k2 = 16 * wid + kkk;
        w0[kkk] = *(const ull*)(Wh + (size_t)n0 * HH + 2 * k2);
        w1[kkk] = *(const ull*)(Wh + (size_t)(n0 + 1) * HH + 2 * k2);
    }

    const int rbl = tid >> 6;
    const int rnl = tid & 63;
    const int rn = n_base + rnl;

    const unsigned base = ld_acq(&g_flag[dir][bg][ns][0]);
    const ull* hwarp = (const ull*)hs + 16 * wid;

    for (int s = 0; s < TT; s++) {
        const int t = dir ? (TT - 1 - s) : s;
        const float* __restrict__ hin =
            (s == 0) ? h0 : (const float*)g_h[dir][s & 1];
        float* __restrict__ hout = (float*)g_h[dir][(s & 1) ^ 1];

#pragma unroll
        for (int i = 0; i < 2; i++) {
            int idx = tid + 512 * i;
            int b = idx >> 7, c = idx & 127;
            float4 v = *(const float4*)(hin + (size_t)(b_base + b) * HH + 4 * c);
            *(float4*)&hs[b * HS2 + 2 * c] = v;
        }
        float xpv = g_xp[dir][t][b_base + rbl][rn];
        __syncthreads();

        ull acc[16];
#pragma unroll
        for (int i = 0; i < 16; i++) acc[i] = 0ull;
#pragma unroll
        for (int kkk = 0; kkk < 16; kkk++) {
            ull ha = hwarp[0 * HS2 + kkk];
            ull hb = hwarp[1 * HS2 + kkk];
            ull hc = hwarp[2 * HS2 + kkk];
            ull hd = hwarp[3 * HS2 + kkk];
            ull he = hwarp[4 * HS2 + kkk];
            ull hf = hwarp[5 * HS2 + kkk];
            ull hg = hwarp[6 * HS2 + kkk];
            ull hh = hwarp[7 * HS2 + kkk];
            fma2(acc[0], ha, w0[kkk]); fma2(acc[8],  ha, w1[kkk]);
            fma2(acc[1], hb, w0[kkk]); fma2(acc[9],  hb, w1[kkk]);
            fma2(acc[2], hc, w0[kkk]); fma2(acc[10], hc, w1[kkk]);
            fma2(acc[3], hd, w0[kkk]); fma2(acc[11], hd, w1[kkk]);
            fma2(acc[4], he, w0[kkk]); fma2(acc[12], he, w1[kkk]);
            fma2(acc[5], hf, w0[kkk]); fma2(acc[13], hf, w1[kkk]);
            fma2(acc[6], hg, w0[kkk]); fma2(acc[14], hg, w1[kkk]);
            fma2(acc[7], hh, w0[kkk]); fma2(acc[15], hh, w1[kkk]);
        }

        {
            ull* rp = red + (size_t)wid * RP + 2 * lane;
#pragma unroll
            for (int b = 0; b < 8; b++)
                *(ulonglong2*)(rp + b * 64) =
                    make_ulonglong2(acc[b], acc[8 + b]);
        }
        __syncthreads();

        ull ssum = red[tid];
#pragma unroll
        for (int k = 1; k < 16; k++) ssum = add2(ssum, red[k * RP + tid]);
        float2 f = unpack2(ssum);
        float v = tanhf(f.x + f.y + xpv);
        const int rb = b_base + rbl;

        if (s < TT - 1) {
            hout[(size_t)rb * HH + rn] = v;
            __syncthreads();
            if (tid == 0) st_rel(&g_flag[dir][bg][ns][0], base + s + 1);
            out[((size_t)rb * TT + t) * (2 * HH) + (size_t)dir * HH + rn] = v;
            if (tid < 8) {
                const unsigned tgt = base + (unsigned)(s + 1);
                const unsigned* f8 = &g_flag[dir][bg][tid][0];
                while (ld_acq(f8) < tgt) {}
            }
            __syncthreads();
        } else {
            out[((size_t)rb * TT + t) * (2 * HH) + (size_t)dir * HH + rn] = v;
            float* hT = out + (size_t)BB * TT * 2 * HH + (size_t)dir * BB * HH;
            hT[(size_t)rb * HH + rn] = v;
        }
    }
}

extern "C" void kernel_launch(void* const* d_in, const int* in_sizes, int n_in,
                              void* d_out, int out_size) {
    const float* x     = (const float*)d_in[0];
    const float* h0f   = (const float*)d_in[1];
    const float* h0b   = (const float*)d_in[2];
    const float* Wxf_w = (const float*)d_in[3];
    const float* Wxf_b = (const float*)d_in[4];
    const float* Whf_w = (const float*)d_in[5];
    const float* Wxb_w = (const float*)d_in[6];
    const float* Wxb_b = (const float*)d_in[7];
    const float* Whb_w = (const float*)d_in[8];
    float* out = (float*)d_out;

    static int attr_set = 0;
    if (!attr_set) {
        cudaFuncSetAttribute(rnn_persist,
                             cudaFuncAttributeMaxDynamicSharedMemorySize,
                             SMEM_TOTAL);
        cudaFuncSetAttribute(xproj_mma,
                             cudaFuncAttributeMaxDynamicSharedMemorySize,
                             XSMEM);
        attr_set = 1;
    }

    int nblk = (NX4 + NW4 + 255) / 256;
    split_kernel<<<nblk, 256>>>(x, Wxf_w, Wxb_w);
    xproj_mma<<<dim3(8, TT, 2), 256, XSMEM>>>(Wxf_b, Wxb_b);
    rnn_persist<<<128, 512, SMEM_TOTAL>>>(Whf_w, Whb_w, h0f, h0b, out);
}

// round 15
// speedup vs baseline: 1.1155x; 1.1155x over previous
#include <cuda_runtime.h>

#define TT 512
#define BB 64
#define II 512
#define HH 512

// rnn_persist smem layout (element strides)
#define HS2 258     // float2 stride per batch row of h
#define RP  520     // ull stride per ks plane in reduction (512 used)
#define RED_OFF (8 * HS2 * 8)                  // 16512
#define SMEM_TOTAL (RED_OFF + 16 * RP * 8)     // 83072

// Static device scratch (no allocations allowed)
__device__ float g_xp[2][TT][BB][HH];      // input projections per direction
__device__ float g_h[2][2][BB][HH];        // [dir][buf][b][h] double-buffered state
__device__ unsigned g_flag[2][8][8][32];   // [dir][bgroup][nslice] flags, 128B padded

typedef unsigned long long ull;

__device__ __forceinline__ void fma2(ull& acc, ull a, ull b) {
    asm("fma.rn.f32x2 %0, %1, %2, %0;" : "+l"(acc) : "l"(a), "l"(b));
}
__device__ __forceinline__ ull add2(ull a, ull b) {
    ull r; asm("add.rn.f32x2 %0, %1, %2;" : "=l"(r) : "l"(a), "l"(b)); return r;
}
__device__ __forceinline__ float2 unpack2(ull v) {
    float2 r; asm("mov.b64 {%0, %1}, %2;" : "=f"(r.x), "=f"(r.y) : "l"(v)); return r;
}
__device__ __forceinline__ unsigned ld_acq(const unsigned* p) {
    unsigned v; asm volatile("ld.acquire.gpu.u32 %0, [%1];" : "=r"(v) : "l"(p) : "memory");
    return v;
}
__device__ __forceinline__ void st_rel(unsigned* p, unsigned v) {
    asm volatile("st.release.gpu.u32 [%0], %1;" :: "l"(p), "r"(v) : "memory");
}

// ---------------------------------------------------------------------------
// Phase 1: xp[dir][t][b][n] = sum_i x[b][t][i] * W[n][i] + bias[n]
// (proven scalar FFMA2 version)
// ---------------------------------------------------------------------------
__global__ __launch_bounds__(256) void xproj_kernel(
    const float* __restrict__ x,
    const float* __restrict__ Wf, const float* __restrict__ bf,
    const float* __restrict__ Wb, const float* __restrict__ bbias) {
    const int dir = blockIdx.z;
    const float* __restrict__ W    = dir ? Wb : Wf;
    const float* __restrict__ bias = dir ? bbias : bf;
    const int t = blockIdx.y;
    const int n_base = blockIdx.x * 64;

    __shared__ float2 a2[8][66];   // [k2][m]
    __shared__ float2 b2[8][66];   // [k2][n]

    const int tid = threadIdx.x;
    const int w = tid >> 5, lane = tid & 31;
    const int mgrp = ((w >> 1) << 2) | (lane >> 3);  // 0..15
    const int ngrp = ((w & 1) << 3) | (lane & 7);    // 0..15
    const int m0 = mgrp << 2, n0l = ngrp << 2;

    const int lr = tid >> 2;
    const int lq = (tid & 3) << 2;
    const float* arow = x + ((size_t)lr * TT + t) * II + lq;
    const float* brow = W + (size_t)(n_base + lr) * II + lq;

    ull acc[4][4];
#pragma unroll
    for (int i = 0; i < 4; i++)
#pragma unroll
        for (int j = 0; j < 4; j++) acc[i][j] = 0ull;

    for (int st = 0; st < 32; st++) {
        float4 pa = *(const float4*)(arow + st * 16);
        float4 pb = *(const float4*)(brow + st * 16);
        __syncthreads();
        a2[(lq >> 1) + 0][lr] = make_float2(pa.x, pa.y);
        a2[(lq >> 1) + 1][lr] = make_float2(pa.z, pa.w);
        b2[(lq >> 1) + 0][lr] = make_float2(pb.x, pb.y);
        b2[(lq >> 1) + 1][lr] = make_float2(pb.z, pb.w);
        __syncthreads();
#pragma unroll
        for (int k2 = 0; k2 < 8; k2++) {
            ulonglong2 av0 = *(const ulonglong2*)&a2[k2][m0];
            ulonglong2 av1 = *(const ulonglong2*)&a2[k2][m0 + 2];
            ulonglong2 bv0 = *(const ulonglong2*)&b2[k2][n0l];
            ulonglong2 bv1 = *(const ulonglong2*)&b2[k2][n0l + 2];
            ull am[4] = {av0.x, av0.y, av1.x, av1.y};
            ull bn[4] = {bv0.x, bv0.y, bv1.x, bv1.y};
#pragma unroll
            for (int i = 0; i < 4; i++)
#pragma unroll
                for (int j = 0; j < 4; j++)
                    fma2(acc[i][j], am[i], bn[j]);
        }
    }

    float4 bv = *(const float4*)(bias + n_base + n0l);
#pragma unroll
    for (int i = 0; i < 4; i++) {
        float2 s0 = unpack2(acc[i][0]);
        float2 s1 = unpack2(acc[i][1]);
        float2 s2 = unpack2(acc[i][2]);
        float2 s3 = unpack2(acc[i][3]);
        float4 v;
        v.x = s0.x + s0.y + bv.x;
        v.y = s1.x + s1.y + bv.y;
        v.z = s2.x + s2.y + bv.z;
        v.w = s3.x + s3.y + bv.w;
        *(float4*)&g_xp[dir][t][m0 + i][n_base + n0l] = v;
    }
}

// ---------------------------------------------------------------------------
// Phase 2: persistent recurrence. 128 CTAs (64/dir), 512 threads, 1 CTA/SM.
// Per dir: 8 b-groups x 8 n-slices; CTA tile 8b x 64n.
// Weights in registers (k-split 16, thread 2n x 8b). h loads LDS.128
// (2 k-pairs per broadcast load). 16-plane reduce; 8-CTA flag barrier.
// ---------------------------------------------------------------------------
__global__ __launch_bounds__(512, 1) void rnn_persist(
    const float* __restrict__ Whf, const float* __restrict__ Whb,
    const float* __restrict__ h0f, const float* __restrict__ h0b,
    float* __restrict__ out) {
    extern __shared__ char smem[];
    float2* hs = (float2*)smem;                 // [8][HS2]
    ull* red   = (ull*)(smem + RED_OFF);        // [16][RP]

    const int cta = blockIdx.x;
    const int dir = cta & 1;
    const int rest = cta >> 1;              // 0..63
    const int bg = rest >> 3;               // b-group 0..7
    const int ns = rest & 7;                // n-slice 0..7
    const int b_base = 8 * bg;
    const int n_base = 64 * ns;
    const float* __restrict__ Wh = dir ? Whb : Whf;
    const float* __restrict__ h0 = dir ? h0b : h0f;
    const int tid = threadIdx.x;
    const int wid = tid >> 5;               // warp = k-slice 0..15 (16 k2 each)
    const int lane = tid & 31;
    const int n0 = n_base + 2 * lane;       // this thread's two n columns

    // ---- one-time weight fill into REGISTERS ----
    ull w0[16], w1[16];
#pragma unroll
    for (int kkk = 0; kkk < 16; kkk++) {
        int k2 = 16 * wid + kkk;
        w0[kkk] = *(const ull*)(Wh + (size_t)n0 * HH + 2 * k2);
        w1[kkk] = *(const ull*)(Wh + (size_t)(n0 + 1) * HH + 2 * k2);
    }

    const int rbl = tid >> 6;
    const int rnl = tid & 63;
    const int rn = n_base + rnl;

    const unsigned base = ld_acq(&g_flag[dir][bg][ns][0]);
    const ulonglong2* hwarp2 = (const ulonglong2*)((const ull*)hs + 16 * wid);

    for (int s = 0; s < TT; s++) {
        const int t = dir ? (TT - 1 - s) : s;
        const float* __restrict__ hin =
            (s == 0) ? h0 : (const float*)g_h[dir][s & 1];
        float* __restrict__ hout = (float*)g_h[dir][(s & 1) ^ 1];

        // ---- stage 8 x 512 h into hs (1024 float4, 2 per thread) ----
#pragma unroll
        for (int i = 0; i < 2; i++) {
            int idx = tid + 512 * i;
            int b = idx >> 7, c = idx & 127;
            float4 v = *(const float4*)(hin + (size_t)(b_base + b) * HH + 4 * c);
            *(float4*)&hs[b * HS2 + 2 * c] = v;
        }
        float xpv = g_xp[dir][t][b_base + rbl][rn];
        __syncthreads();

        // ---- mainloop: 2n x 8b; w in regs; h broadcast LDS.128 (2 k2) ----
        ull acc[16];
#pragma unroll
        for (int i = 0; i < 16; i++) acc[i] = 0ull;
#pragma unroll
        for (int kk = 0; kk < 8; kk++) {
            // HS2 is even so b*HS2 + 16*wid + 2*kk stays 16B-aligned
            ulonglong2 ha = hwarp2[(0 * HS2) / 2 + kk];
            ulonglong2 hb = hwarp2[(1 * HS2) / 2 + kk + ((1 * HS2) & 1 ? 0 : 0)];
            ulonglong2 hc = hwarp2[(2 * HS2) / 2 + kk];
            ulonglong2 hd = hwarp2[(3 * HS2) / 2 + kk];
            ulonglong2 he = hwarp2[(4 * HS2) / 2 + kk];
            ulonglong2 hf = hwarp2[(5 * HS2) / 2 + kk];
            ulonglong2 hg = hwarp2[(6 * HS2) / 2 + kk];
            ulonglong2 hh = hwarp2[(7 * HS2) / 2 + kk];
            ull wa0 = w0[2 * kk], wa1 = w0[2 * kk + 1];
            ull wb0 = w1[2 * kk], wb1 = w1[2 * kk + 1];
            fma2(acc[0], ha.x, wa0); fma2(acc[0], ha.y, wa1);
            fma2(acc[8], ha.x, wb0); fma2(acc[8], ha.y, wb1);
            fma2(acc[1], hb.x, wa0); fma2(acc[1], hb.y, wa1);
            fma2(acc[9], hb.x, wb0); fma2(acc[9], hb.y, wb1);
            fma2(acc[2], hc.x, wa0); fma2(acc[2], hc.y, wa1);
            fma2(acc[10], hc.x, wb0); fma2(acc[10], hc.y, wb1);
            fma2(acc[3], hd.x, wa0); fma2(acc[3], hd.y, wa1);
            fma2(acc[11], hd.x, wb0); fma2(acc[11], hd.y, wb1);
            fma2(acc[4], he.x, wa0); fma2(acc[4], he.y, wa1);
            fma2(acc[12], he.x, wb0); fma2(acc[12], he.y, wb1);
            fma2(acc[5], hf.x, wa0); fma2(acc[5], hf.y, wa1);
            fma2(acc[13], hf.x, wb0); fma2(acc[13], hf.y, wb1);
            fma2(acc[6], hg.x, wa0); fma2(acc[6], hg.y, wa1);
            fma2(acc[14], hg.x, wb0); fma2(acc[14], hg.y, wb1);
            fma2(acc[7], hh.x, wa0); fma2(acc[7], hh.y, wa1);
            fma2(acc[15], hh.x, wb0); fma2(acc[15], hh.y, wb1);
        }

        // ---- partials: red[wid][b*64 + 2*lane + j] = acc[j*8+b] ----
        {
            ull* rp = red + (size_t)wid * RP + 2 * lane;
#pragma unroll
            for (int b = 0; b < 8; b++)
                *(ulonglong2*)(rp + b * 64) =
                    make_ulonglong2(acc[b], acc[8 + b]);
        }
        __syncthreads();

        // ---- 16-way reduce (1 output/thread) + tanh ----
        ull ssum = red[tid];
#pragma unroll
        for (int k = 1; k < 16; k++) ssum = add2(ssum, red[k * RP + tid]);
        float2 f = unpack2(ssum);
        float v = tanhf(f.x + f.y + xpv);
        const int rb = b_base + rbl;

        if (s < TT - 1) {
            hout[(size_t)rb * HH + rn] = v;
            __syncthreads();                 // all hout writes issued
            if (tid == 0) st_rel(&g_flag[dir][bg][ns][0], base + s + 1);
            // y store off the inter-CTA critical path
            out[((size_t)rb * TT + t) * (2 * HH) + (size_t)dir * HH + rn] = v;
            if (tid < 8) {
                const unsigned tgt = base + (unsigned)(s + 1);
                const unsigned* f8 = &g_flag[dir][bg][tid][0];
                while (ld_acq(f8) < tgt) {}
            }
            __syncthreads();
        } else {
            out[((size_t)rb * TT + t) * (2 * HH) + (size_t)dir * HH + rn] = v;
            float* hT = out + (size_t)BB * TT * 2 * HH + (size_t)dir * BB * HH;
            hT[(size_t)rb * HH + rn] = v;
        }
    }
}

extern "C" void kernel_launch(void* const* d_in, const int* in_sizes, int n_in,
                              void* d_out, int out_size) {
    const float* x     = (const float*)d_in[0];
    const float* h0f   = (const float*)d_in[1];
    const float* h0b   = (const float*)d_in[2];
    const float* Wxf_w = (const float*)d_in[3];
    const float* Wxf_b = (const float*)d_in[4];
    const float* Whf_w = (const float*)d_in[5];
    const float* Wxb_w = (const float*)d_in[6];
    const float* Wxb_b = (const float*)d_in[7];
    const float* Whb_w = (const float*)d_in[8];
    float* out = (float*)d_out;

    static int smem_set = 0;
    if (!smem_set) {
        cudaFuncSetAttribute(rnn_persist,
                             cudaFuncAttributeMaxDynamicSharedMemorySize,
                             SMEM_TOTAL);
        smem_set = 1;
    }

    xproj_kernel<<<dim3(HH / 64, TT, 2), 256>>>(x, Wxf_w, Wxf_b, Wxb_w, Wxb_b);
    rnn_persist<<<128, 512, SMEM_TOTAL>>>(Whf_w, Whb_w, h0f, h0b, out);
}